// round 2
// baseline (speedup 1.0000x reference)
#include <cuda_runtime.h>
#include <cstdint>
#include <math.h>

#define N_Q     4096
#define N_KV    32768
#define C_DIM   256
#define KNN     100
#define THREADS 256
#define LN_EPS  1e-5f

struct SmemLayout {
    float        d2[N_KV];       // 131072 B
    unsigned int hist[256];
    float        qs[C_DIM];
    float        logits[128];
    float        wts[128];
    int          sel[128];
    int          eq_buf[64];
    float        red1[8];
    float        red2[8];
    unsigned int pval_s;
    int          krem_s;
    int          n_less;
    int          eq_ctr;
    float        sm_max, sm_sum, sm_mean, sm_rstd;
};

extern __shared__ unsigned char smem_raw[];

__global__ __launch_bounds__(THREADS, 1)
void sparse_attn_kernel(const float* __restrict__ q_feat,
                        const float* __restrict__ k_feat,
                        const float* __restrict__ v_feat,
                        const float* __restrict__ q_pos,
                        const float* __restrict__ k_pos,
                        const float* __restrict__ gamma,
                        const float* __restrict__ beta,
                        float* __restrict__ out)
{
    SmemLayout& s = *reinterpret_cast<SmemLayout*>(smem_raw);
    const int i    = blockIdx.x;
    const int tid  = threadIdx.x;
    const int lane = tid & 31;
    const int wid  = tid >> 5;

    // ---- Phase 1: pairwise squared distances into SMEM ----
    const float qx = q_pos[i * 3 + 0];
    const float qy = q_pos[i * 3 + 1];
    const float qz = q_pos[i * 3 + 2];
    const float sq = qx * qx + qy * qy + qz * qz;

    for (int j = tid; j < N_KV; j += THREADS) {
        float kx = k_pos[3 * j + 0];
        float ky = k_pos[3 * j + 1];
        float kz = k_pos[3 * j + 2];
        float kk  = kx * kx + ky * ky + kz * kz;
        float dot = qx * kx + qy * ky + qz * kz;
        float d2  = sq + kk - 2.0f * dot;
        s.d2[j] = fmaxf(d2, 0.0f);
    }
    __syncthreads();

    // ---- Phase 2: MSB radix select the 100th smallest key ----
    // d2 >= 0 so float bits are order-monotone.
    unsigned pmask = 0u, pval = 0u;
    int krem = KNN;
    for (int shift = 24; shift >= 0; shift -= 8) {
        s.hist[tid] = 0u;           // THREADS == 256 bins
        __syncthreads();
        for (int j = tid; j < N_KV; j += THREADS) {
            unsigned key = __float_as_uint(s.d2[j]);
            if ((key & pmask) == pval)
                atomicAdd(&s.hist[(key >> shift) & 255u], 1u);
        }
        __syncthreads();
        if (tid == 0) {
            int cum = 0, d = 0;
            for (; d < 256; d++) {
                int c = (int)s.hist[d];
                if (cum + c >= krem) break;
                cum += c;
            }
            s.pval_s = pval | ((unsigned)d << shift);
            s.krem_s = krem - cum;
        }
        __syncthreads();
        pval = s.pval_s;
        krem = s.krem_s;
        pmask |= 255u << shift;
        __syncthreads();
    }
    const unsigned T = pval;        // key bits of the 100th smallest
    const int need_eq = krem;       // how many ties at T to take

    // ---- Phase 3: collect the selected 100 indices ----
    if (tid == 0) { s.n_less = 0; s.eq_ctr = 0; }
    __syncthreads();
    for (int j = tid; j < N_KV; j += THREADS) {
        unsigned key = __float_as_uint(s.d2[j]);
        if (key < T) {
            int p = atomicAdd(&s.n_less, 1);
            s.sel[p] = j;
        } else if (key == T) {
            int p = atomicAdd(&s.eq_ctr, 1);
            if (p < 64) s.eq_buf[p] = j;
        }
    }
    __syncthreads();
    if (tid == 0) {
        int nl = s.n_less;
        int ne = s.eq_ctr; if (ne > 64) ne = 64;
        // smallest indices first among ties (matches stable top_k)
        for (int a = 1; a < ne; a++) {
            int v = s.eq_buf[a]; int b = a - 1;
            while (b >= 0 && s.eq_buf[b] > v) { s.eq_buf[b + 1] = s.eq_buf[b]; b--; }
            s.eq_buf[b + 1] = v;
        }
        for (int a = 0; a < need_eq && a < ne; a++) s.sel[nl + a] = s.eq_buf[a];
    }
    __syncthreads();

    // ---- Phase 4: attention logits (warp per logit) ----
    s.qs[tid] = q_feat[(size_t)i * C_DIM + tid];
    __syncthreads();

    for (int j = wid; j < KNN; j += 8) {
        const float* kr = k_feat + (size_t)s.sel[j] * C_DIM;
        float p = 0.0f;
        #pragma unroll
        for (int u = 0; u < 8; u++) {
            int c = lane + 32 * u;
            p += s.qs[c] * kr[c];
        }
        #pragma unroll
        for (int o = 16; o > 0; o >>= 1)
            p += __shfl_xor_sync(0xffffffffu, p, o);
        if (lane == 0) s.logits[j] = p * 0.0625f;   // C^-0.5 = 1/16
    }
    __syncthreads();

    // ---- Phase 5: softmax over 100 logits ----
    if (wid == 0) {
        float m = -INFINITY;
        #pragma unroll
        for (int u = 0; u < 4; u++) {
            int j = lane + 32 * u;
            if (j < KNN) m = fmaxf(m, s.logits[j]);
        }
        #pragma unroll
        for (int o = 16; o > 0; o >>= 1)
            m = fmaxf(m, __shfl_xor_sync(0xffffffffu, m, o));
        float ssum = 0.0f;
        #pragma unroll
        for (int u = 0; u < 4; u++) {
            int j = lane + 32 * u;
            if (j < KNN) ssum += expf(s.logits[j] - m);
        }
        #pragma unroll
        for (int o = 16; o > 0; o >>= 1)
            ssum += __shfl_xor_sync(0xffffffffu, ssum, o);
        if (lane == 0) { s.sm_max = m; s.sm_sum = ssum; }
    }
    __syncthreads();
    if (tid < KNN)
        s.wts[tid] = expf(s.logits[tid] - s.sm_max) / s.sm_sum;
    __syncthreads();

    // ---- Phase 6: weighted V gather (thread t owns channel t) ----
    float acc = 0.0f;
    #pragma unroll 4
    for (int j = 0; j < KNN; j++)
        acc += s.wts[j] * v_feat[(size_t)s.sel[j] * C_DIM + tid];

    // res.at[arange].set(x) covers every row -> y = x + x = 2x
    float y = 2.0f * acc;

    // ---- Phase 7: LayerNorm over C=256 ----
    float s1 = y, s2 = y * y;
    #pragma unroll
    for (int o = 16; o > 0; o >>= 1) {
        s1 += __shfl_xor_sync(0xffffffffu, s1, o);
        s2 += __shfl_xor_sync(0xffffffffu, s2, o);
    }
    if (lane == 0) { s.red1[wid] = s1; s.red2[wid] = s2; }
    __syncthreads();
    if (wid == 0) {
        float a = (lane < 8) ? s.red1[lane] : 0.0f;
        float b = (lane < 8) ? s.red2[lane] : 0.0f;
        #pragma unroll
        for (int o = 4; o > 0; o >>= 1) {
            a += __shfl_xor_sync(0xffffffffu, a, o);
            b += __shfl_xor_sync(0xffffffffu, b, o);
        }
        if (lane == 0) {
            float mean = a * (1.0f / C_DIM);
            float var  = b * (1.0f / C_DIM) - mean * mean;
            s.sm_mean = mean;
            s.sm_rstd = rsqrtf(var + LN_EPS);
        }
    }
    __syncthreads();

    out[(size_t)i * C_DIM + tid] =
        (y - s.sm_mean) * s.sm_rstd * gamma[tid] + beta[tid];
}

extern "C" void kernel_launch(void* const* d_in, const int* in_sizes, int n_in,
                              void* d_out, int out_size)
{
    // inputs: 0=res_feat (dead: scatter covers all rows), 1=q_feat, 2=k_feat,
    //         3=v_feat, 4=q_pos, 5=k_pos, 6=gamma, 7=beta
    const float* q_feat = (const float*)d_in[1];
    const float* k_feat = (const float*)d_in[2];
    const float* v_feat = (const float*)d_in[3];
    const float* q_pos  = (const float*)d_in[4];
    const float* k_pos  = (const float*)d_in[5];
    const float* gamma  = (const float*)d_in[6];
    const float* beta   = (const float*)d_in[7];
    float* out = (float*)d_out;

    const int smem_bytes = (int)sizeof(SmemLayout);
    cudaFuncSetAttribute(sparse_attn_kernel,
                         cudaFuncAttributeMaxDynamicSharedMemorySize, smem_bytes);
    sparse_attn_kernel<<<N_Q, THREADS, smem_bytes>>>(
        q_feat, k_feat, v_feat, q_pos, k_pos, gamma, beta, out);
}

// round 3
// speedup vs baseline: 3.7374x; 3.7374x over previous
#include <cuda_runtime.h>
#include <cstdint>
#include <math.h>

#define N_Q     4096
#define N_KV    32768
#define C_DIM   256
#define KNN     100
#define THREADS 256
#define LN_EPS  1e-5f
#define NWORDS  (N_KV / 2)      // 16384 packed 2x16-bit key words

struct __align__(16) SmemLayout {
    unsigned int keyw[NWORDS];          // 65536 B: keys 2w (lo), 2w+1 (hi)
    unsigned int hist[256];
    float        qs[C_DIM];             // offset 66560, 16B aligned
    float        logits[128];
    float        wts[128];
    int          sel[128];
    int          eq_idx[64];
    float        eq_d2[64];
    float        red1[8];
    float        red2[8];
    unsigned int bsel;                  // selected radix digit
    int          krem_s;
    int          n_less;
    int          eq_ctr;
    float        sm_max, sm_sum, sm_mean, sm_rstd;
};

extern __shared__ unsigned char smem_raw[];

__global__ __launch_bounds__(THREADS)
void sparse_attn_kernel(const float* __restrict__ q_feat,
                        const float* __restrict__ k_feat,
                        const float* __restrict__ v_feat,
                        const float* __restrict__ q_pos,
                        const float* __restrict__ k_pos,
                        const float* __restrict__ gamma,
                        const float* __restrict__ beta,
                        float* __restrict__ out)
{
    SmemLayout& s = *reinterpret_cast<SmemLayout*>(smem_raw);
    const int i    = blockIdx.x;
    const int tid  = threadIdx.x;
    const int lane = tid & 31;
    const int wid  = tid >> 5;

    const float qx = q_pos[i * 3 + 0];
    const float qy = q_pos[i * 3 + 1];
    const float qz = q_pos[i * 3 + 2];
    const float sq = qx * qx + qy * qy + qz * qz;

    // ---- Phase 1: distances -> 16-bit keys, fused high-byte histogram ----
    s.hist[tid] = 0u;
    if (tid == 0) { s.n_less = 0; s.eq_ctr = 0; }
    __syncthreads();

    for (int w = tid; w < NWORDS; w += THREADS) {
        const float* kp = k_pos + 6 * (size_t)w;   // points 2w, 2w+1
        float ax = kp[0], ay = kp[1], az = kp[2];
        float bx = kp[3], by = kp[4], bz = kp[5];
        float d2a = sq + ax * ax + ay * ay + az * az
                  - 2.0f * (qx * ax + qy * ay + qz * az);
        float d2b = sq + bx * bx + by * by + bz * bz
                  - 2.0f * (qx * bx + qy * by + qz * bz);
        unsigned ka = __float_as_uint(fmaxf(d2a, 0.0f)) >> 16;
        unsigned kb = __float_as_uint(fmaxf(d2b, 0.0f)) >> 16;
        s.keyw[w] = ka | (kb << 16);
        atomicAdd(&s.hist[ka >> 8], 1u);
        atomicAdd(&s.hist[kb >> 8], 1u);
    }
    __syncthreads();

    // ---- Parallel 256-bin prefix-select: high byte ----
    int krem = KNN;
    {
        int cum = 0, cthis = 0;
        #pragma unroll 8
        for (int b = 0; b < 256; ++b) {
            int c = (int)s.hist[b];
            if (b < tid) cum += c;
            if (b == tid) cthis = c;
        }
        if (krem > cum && krem <= cum + cthis) {
            s.bsel = (unsigned)tid;
            s.krem_s = krem - cum;
        }
    }
    __syncthreads();
    const unsigned hb = s.bsel;
    krem = s.krem_s;
    __syncthreads();

    // ---- Pass B: low-byte histogram restricted to high byte == hb ----
    s.hist[tid] = 0u;
    __syncthreads();
    for (int w = tid; w < NWORDS; w += THREADS) {
        unsigned word = s.keyw[w];
        unsigned ka = word & 0xffffu, kb = word >> 16;
        if ((ka >> 8) == hb) atomicAdd(&s.hist[ka & 255u], 1u);
        if ((kb >> 8) == hb) atomicAdd(&s.hist[kb & 255u], 1u);
    }
    __syncthreads();
    {
        int cum = 0, cthis = 0;
        #pragma unroll 8
        for (int b = 0; b < 256; ++b) {
            int c = (int)s.hist[b];
            if (b < tid) cum += c;
            if (b == tid) cthis = c;
        }
        if (krem > cum && krem <= cum + cthis) {
            s.bsel = (hb << 8) | (unsigned)tid;
            s.krem_s = krem - cum;
        }
    }
    __syncthreads();
    const unsigned T16 = s.bsel;       // 16-bit key of the 100th smallest
    const int need_eq = s.krem_s;      // how many == T16 to take
    __syncthreads();

    // ---- Collection: keys < T16 definitely in; == T16 are candidates ----
    for (int w = tid; w < NWORDS; w += THREADS) {
        unsigned word = s.keyw[w];
        unsigned ka = word & 0xffffu, kb = word >> 16;
        int ja = 2 * w, jb = 2 * w + 1;
        if (ka < T16)       s.sel[atomicAdd(&s.n_less, 1)] = ja;
        else if (ka == T16) { int p = atomicAdd(&s.eq_ctr, 1); if (p < 64) s.eq_idx[p] = ja; }
        if (kb < T16)       s.sel[atomicAdd(&s.n_less, 1)] = jb;
        else if (kb == T16) { int p = atomicAdd(&s.eq_ctr, 1); if (p < 64) s.eq_idx[p] = jb; }
    }
    __syncthreads();

    // ---- Tie resolution at full fp32 precision (tiny candidate set) ----
    int ne = s.eq_ctr; if (ne > 64) ne = 64;
    if (tid < ne) {
        int j = s.eq_idx[tid];
        float kx = k_pos[3 * j], ky = k_pos[3 * j + 1], kz = k_pos[3 * j + 2];
        float d2 = sq + kx * kx + ky * ky + kz * kz
                 - 2.0f * (qx * kx + qy * ky + qz * kz);
        s.eq_d2[tid] = fmaxf(d2, 0.0f);
    }
    __syncthreads();
    if (tid == 0) {
        int nl = s.n_less;
        int take = need_eq < ne ? need_eq : ne;
        for (int a = 0; a < take; ++a) {          // selection sort, a few elems
            int best = a;
            for (int b = a + 1; b < ne; ++b) {
                if (s.eq_d2[b] < s.eq_d2[best] ||
                    (s.eq_d2[b] == s.eq_d2[best] && s.eq_idx[b] < s.eq_idx[best]))
                    best = b;
            }
            float td = s.eq_d2[a]; s.eq_d2[a] = s.eq_d2[best]; s.eq_d2[best] = td;
            int   ti = s.eq_idx[a]; s.eq_idx[a] = s.eq_idx[best]; s.eq_idx[best] = ti;
            s.sel[nl + a] = s.eq_idx[a];
        }
    }
    __syncthreads();

    // ---- Phase 4: attention logits (warp per logit, float4) ----
    s.qs[tid] = q_feat[(size_t)i * C_DIM + tid];
    __syncthreads();
    const float4* qs4 = reinterpret_cast<const float4*>(s.qs);

    for (int j = wid; j < KNN; j += 8) {
        const float4* kr = reinterpret_cast<const float4*>(
            k_feat + (size_t)s.sel[j] * C_DIM);
        float4 a0 = kr[lane],      a1 = kr[lane + 32];
        float4 b0 = qs4[lane],     b1 = qs4[lane + 32];
        float p = a0.x * b0.x + a0.y * b0.y + a0.z * b0.z + a0.w * b0.w
                + a1.x * b1.x + a1.y * b1.y + a1.z * b1.z + a1.w * b1.w;
        #pragma unroll
        for (int o = 16; o > 0; o >>= 1)
            p += __shfl_xor_sync(0xffffffffu, p, o);
        if (lane == 0) s.logits[j] = p * 0.0625f;   // C^-0.5 = 1/16
    }
    __syncthreads();

    // ---- Phase 5: softmax over 100 logits ----
    if (wid == 0) {
        float m = -INFINITY;
        #pragma unroll
        for (int u = 0; u < 4; u++) {
            int j = lane + 32 * u;
            if (j < KNN) m = fmaxf(m, s.logits[j]);
        }
        #pragma unroll
        for (int o = 16; o > 0; o >>= 1)
            m = fmaxf(m, __shfl_xor_sync(0xffffffffu, m, o));
        float ssum = 0.0f;
        #pragma unroll
        for (int u = 0; u < 4; u++) {
            int j = lane + 32 * u;
            if (j < KNN) ssum += expf(s.logits[j] - m);
        }
        #pragma unroll
        for (int o = 16; o > 0; o >>= 1)
            ssum += __shfl_xor_sync(0xffffffffu, ssum, o);
        if (lane == 0) { s.sm_max = m; s.sm_sum = ssum; }
    }
    __syncthreads();
    if (tid < KNN)
        s.wts[tid] = expf(s.logits[tid] - s.sm_max) / s.sm_sum;
    __syncthreads();

    // ---- Phase 6: weighted V gather (thread t owns channel t) ----
    float acc = 0.0f;
    #pragma unroll 10
    for (int j = 0; j < KNN; j++)
        acc += s.wts[j] * v_feat[(size_t)s.sel[j] * C_DIM + tid];

    // res.at[arange].set(x) covers every row -> y = x + x = 2x
    float y = 2.0f * acc;

    // ---- Phase 7: LayerNorm over C=256 ----
    float s1 = y, s2 = y * y;
    #pragma unroll
    for (int o = 16; o > 0; o >>= 1) {
        s1 += __shfl_xor_sync(0xffffffffu, s1, o);
        s2 += __shfl_xor_sync(0xffffffffu, s2, o);
    }
    if (lane == 0) { s.red1[wid] = s1; s.red2[wid] = s2; }
    __syncthreads();
    if (wid == 0) {
        float a = (lane < 8) ? s.red1[lane] : 0.0f;
        float b = (lane < 8) ? s.red2[lane] : 0.0f;
        #pragma unroll
        for (int o = 4; o > 0; o >>= 1) {
            a += __shfl_xor_sync(0xffffffffu, a, o);
            b += __shfl_xor_sync(0xffffffffu, b, o);
        }
        if (lane == 0) {
            float mean = a * (1.0f / C_DIM);
            float var  = b * (1.0f / C_DIM) - mean * mean;
            s.sm_mean = mean;
            s.sm_rstd = rsqrtf(var + LN_EPS);
        }
    }
    __syncthreads();

    out[(size_t)i * C_DIM + tid] =
        (y - s.sm_mean) * s.sm_rstd * gamma[tid] + beta[tid];
}

extern "C" void kernel_launch(void* const* d_in, const int* in_sizes, int n_in,
                              void* d_out, int out_size)
{
    // inputs: 0=res_feat (dead: scatter covers all rows), 1=q_feat, 2=k_feat,
    //         3=v_feat, 4=q_pos, 5=k_pos, 6=gamma, 7=beta
    const float* q_feat = (const float*)d_in[1];
    const float* k_feat = (const float*)d_in[2];
    const float* v_feat = (const float*)d_in[3];
    const float* q_pos  = (const float*)d_in[4];
    const float* k_pos  = (const float*)d_in[5];
    const float* gamma  = (const float*)d_in[6];
    const float* beta   = (const float*)d_in[7];
    float* out = (float*)d_out;

    const int smem_bytes = (int)sizeof(SmemLayout);
    cudaFuncSetAttribute(sparse_attn_kernel,
                         cudaFuncAttributeMaxDynamicSharedMemorySize, smem_bytes);
    sparse_attn_kernel<<<N_Q, THREADS, smem_bytes>>>(
        q_feat, k_feat, v_feat, q_pos, k_pos, gamma, beta, out);
}